// round 4
// baseline (speedup 1.0000x reference)
#include <cuda_runtime.h>
#include <math.h>

#define BDIM 32
#define TDIM 32
#define LDIM 128
#define LOG_L 7
#define LOG_T 5

// ---------------- scratch (static device globals; no allocs allowed) ----------------
__device__ float g_xg1[(size_t)BDIM*TDIM*LDIM*256];   // [B][T][L][4F1]
__device__ float g_xg2[(size_t)TDIM*BDIM*LDIM*512];   // [T][B][L][4F2]
__device__ float g_xg3[(size_t)TDIM*BDIM*LDIM*1024];  // [T][B][L][4F3]
__device__ float g_h1 [(size_t)TDIM*BDIM*LDIM*64];    // [T][B][L][F1]
__device__ float g_h2 [(size_t)TDIM*BDIM*LDIM*128];   // [T][B][L][F2]
__device__ float g_hst[(size_t)BDIM*LDIM*256];
__device__ float g_cst[(size_t)BDIM*LDIM*256];
__device__ float g_gbf[(size_t)BDIM*LDIM*1024];
__device__ float g_prt[(size_t)8*BDIM*1024];
__device__ float g_a1 [(size_t)BDIM*1024];
__device__ float g_a2 [(size_t)BDIM*512];

// ---------------- implicit-GEMM (conv gather) SGEMM: C[M,N] = gather(A)[M,K] @ W[K,N] (+bias) ----
#define BM 128
#define BN 128
#define BK 8

__global__ __launch_bounds__(256) void gemm_conv_kernel(
    const float* __restrict__ A, const float* __restrict__ W,
    const float* __restrict__ bias, float* __restrict__ C,
    int M, int N, int K, int logCin, int convMode)
{
    __shared__ float As[BK][BM];
    __shared__ float Bs[BK][BN];
    int tid = threadIdx.x;
    int m0 = blockIdx.y * BM;
    int n0 = blockIdx.x * BN;
    int tx = tid & 15, ty = tid >> 4;

    int a_row = tid >> 1;          // 0..127
    int a_col = (tid & 1) * 4;     // 0 or 4
    int b_k   = tid >> 5;          // 0..7
    int b_n   = (tid & 31) * 4;

    int Cin = 1 << logCin;
    float acc[8][8];
    #pragma unroll
    for (int i = 0; i < 8; i++)
        #pragma unroll
        for (int j = 0; j < 8; j++) acc[i][j] = 0.f;

    for (int k0 = 0; k0 < K; k0 += BK) {
        int m = m0 + a_row;
        #pragma unroll
        for (int i = 0; i < 4; i++) {
            int kk = k0 + a_col + i;
            float v = 0.f;
            if (m < M && kk < K) {
                if (convMode) {
                    int l  = m & (LDIM - 1);
                    int ks = kk >> logCin;
                    int ci = kk - (ks << logCin);
                    int ll = l + ks - 1;
                    if (ll >= 0 && ll < LDIM)
                        v = A[(size_t)(m - l + ll) * Cin + ci];
                } else {
                    v = A[(size_t)m * K + kk];
                }
            }
            As[a_col + i][a_row] = v;
        }
        {
            int kk = k0 + b_k;
            float4 v = make_float4(0.f, 0.f, 0.f, 0.f);
            if (kk < K && n0 + b_n + 3 < N)
                v = *reinterpret_cast<const float4*>(&W[(size_t)kk * N + n0 + b_n]);
            Bs[b_k][b_n]     = v.x;
            Bs[b_k][b_n + 1] = v.y;
            Bs[b_k][b_n + 2] = v.z;
            Bs[b_k][b_n + 3] = v.w;
        }
        __syncthreads();
        #pragma unroll
        for (int kk = 0; kk < BK; kk++) {
            float af[8], bf[8];
            #pragma unroll
            for (int i = 0; i < 8; i++) af[i] = As[kk][ty * 8 + i];
            #pragma unroll
            for (int j = 0; j < 8; j++) bf[j] = Bs[kk][tx * 8 + j];
            #pragma unroll
            for (int i = 0; i < 8; i++)
                #pragma unroll
                for (int j = 0; j < 8; j++)
                    acc[i][j] += af[i] * bf[j];
        }
        __syncthreads();
    }

    #pragma unroll
    for (int i = 0; i < 8; i++) {
        int m = m0 + ty * 8 + i;
        if (m >= M) continue;
        #pragma unroll
        for (int j = 0; j < 8; j++) {
            int n = n0 + tx * 8 + j;
            if (n >= N) continue;
            float v = acc[i][j];
            if (bias) v += bias[n];
            C[(size_t)m * N + n] = v;
        }
    }
}

// ---------------- LSTM gate fusion ----------------
__device__ __forceinline__ float hsig(float x) {
    return fminf(fmaxf(0.2f * x + 0.5f, 0.f), 1.f);
}

__global__ void gate_kernel(const float* __restrict__ g,
                            const float* __restrict__ xg,
                            float* __restrict__ c, float* __restrict__ h,
                            float* __restrict__ hseq,
                            int F, int logF, int t, int btLayout)
{
    int idx = blockIdx.x * blockDim.x + threadIdx.x;
    int MF = (BDIM * LDIM) << logF;
    if (idx >= MF) return;
    int m = idx >> logF;
    int f = idx - (m << logF);
    size_t xrow;
    if (btLayout) {   // xg layout [B][T][L][4F]
        int b = m >> LOG_L;
        int l = m & (LDIM - 1);
        xrow = ((size_t)(b * TDIM + t) << LOG_L) + l;
    } else {          // xg already offset to timestep t; layout [B*L][4F]
        xrow = (size_t)m;
    }
    size_t gi = (size_t)m * 4 * F + f;
    size_t xi = xrow * 4 * F + f;
    float iv = g[gi]           + xg[xi];
    float fv = g[gi + F]       + xg[xi + F];
    float cv = g[gi + 2 * F]   + xg[xi + 2 * F];
    float ov = g[gi + 3 * F]   + xg[xi + 3 * F];
    float cn = hsig(fv) * c[idx] + hsig(iv) * fmaxf(cv, 0.f);
    c[idx] = cn;
    float hn = hsig(ov) * fmaxf(cn, 0.f);
    h[idx] = hn;
    if (hseq) hseq[idx] = hn;
}

// ---------------- inference BN (in place) ----------------
__global__ void bn_kernel(float* __restrict__ x, const float* __restrict__ gw,
                          const float* __restrict__ be, const float* __restrict__ mu,
                          const float* __restrict__ var, size_t total, int logC)
{
    size_t idx = (size_t)blockIdx.x * blockDim.x + threadIdx.x;
    if (idx >= total) return;
    int C = 1 << logC;
    int ch = (int)(idx & (size_t)(C - 1));
    x[idx] = (x[idx] - mu[ch]) * rsqrtf(var[ch] + 1e-3f) * gw[ch] + be[ch];
}

// ---------------- dense head: split-K small-M GEMM ----------------
__global__ __launch_bounds__(256) void fc_kernel(
    const float* __restrict__ A, const float* __restrict__ W,
    float* __restrict__ partial, int N, int K, int kchunk)
{
    __shared__ float As[32][33];
    int tid = threadIdx.x;
    int n0 = blockIdx.x * 64;
    int col = tid & 63;
    int rq = tid >> 6;          // 0..3
    int k0 = blockIdx.y * kchunk;
    int kend = min(K, k0 + kchunk);
    float acc[8];
    #pragma unroll
    for (int r = 0; r < 8; r++) acc[r] = 0.f;
    int a_m = tid >> 3;         // 0..31
    int a_k = (tid & 7) * 4;
    for (int kb = k0; kb < kend; kb += 32) {
        #pragma unroll
        for (int i = 0; i < 4; i++) {
            int kk = kb + a_k + i;
            As[a_m][a_k + i] = (kk < K) ? A[(size_t)a_m * K + kk] : 0.f;
        }
        __syncthreads();
        #pragma unroll
        for (int kk = 0; kk < 32; kk++) {
            float w = W[(size_t)(kb + kk) * N + n0 + col];
            #pragma unroll
            for (int r = 0; r < 8; r++)
                acc[r] += As[rq * 8 + r][kk] * w;
        }
        __syncthreads();
    }
    #pragma unroll
    for (int r = 0; r < 8; r++) {
        int m = rq * 8 + r;
        partial[((size_t)blockIdx.y * 32 + m) * N + n0 + col] = acc[r];
    }
}

__global__ void fc_reduce_relu(const float* __restrict__ partial,
                               const float* __restrict__ bias,
                               float* __restrict__ out, int N, int KS)
{
    int idx = blockIdx.x * blockDim.x + threadIdx.x;
    if (idx >= 32 * N) return;
    int m = idx / N, n = idx - m * N;
    float s = bias[n];
    for (int ks = 0; ks < KS; ks++)
        s += partial[((size_t)ks * 32 + m) * N + n];
    out[idx] = fmaxf(s, 0.f);
}

__global__ void fc3_softmax(const float* __restrict__ A, const float* __restrict__ W,
                            const float* __restrict__ bias, float* __restrict__ out)
{
    __shared__ float logits[32][5];
    int tid = threadIdx.x;        // 256 threads
    int bm = tid >> 3, j = tid & 7;
    if (bm < 32 && j < 5) {
        float s = bias[j];
        for (int k = 0; k < 512; k++)
            s += A[bm * 512 + k] * W[k * 5 + j];
        logits[bm][j] = s;
    }
    __syncthreads();
    if (bm < 32 && j == 0) {
        float mx = logits[bm][0];
        for (int q = 1; q < 5; q++) mx = fmaxf(mx, logits[bm][q]);
        float e[5], sum = 0.f;
        for (int q = 0; q < 5; q++) { e[q] = expf(logits[bm][q] - mx); sum += e[q]; }
        for (int q = 0; q < 5; q++) out[bm * 5 + q] = e[q] / sum;
    }
}

// ---------------- host orchestration ----------------
extern "C" void kernel_launch(void* const* d_in, const int* in_sizes, int n_in,
                              void* d_out, int out_size)
{
    const float* x   = (const float*)d_in[0];
    const float* Wx1 = (const float*)d_in[1];
    const float* Wh1 = (const float*)d_in[2];
    const float* b1  = (const float*)d_in[3];
    const float* Wx2 = (const float*)d_in[4];
    const float* Wh2 = (const float*)d_in[5];
    const float* b2  = (const float*)d_in[6];
    const float* Wx3 = (const float*)d_in[7];
    const float* Wh3 = (const float*)d_in[8];
    const float* b3  = (const float*)d_in[9];
    const float* g1  = (const float*)d_in[10];
    const float* be1 = (const float*)d_in[11];
    const float* m1  = (const float*)d_in[12];
    const float* v1  = (const float*)d_in[13];
    const float* g2  = (const float*)d_in[14];
    const float* be2 = (const float*)d_in[15];
    const float* m2  = (const float*)d_in[16];
    const float* v2  = (const float*)d_in[17];
    const float* g3  = (const float*)d_in[18];
    const float* be3 = (const float*)d_in[19];
    const float* m3  = (const float*)d_in[20];
    const float* v3  = (const float*)d_in[21];
    const float* D1  = (const float*)d_in[22];
    const float* db1 = (const float*)d_in[23];
    const float* D2  = (const float*)d_in[24];
    const float* db2 = (const float*)d_in[25];
    const float* D3  = (const float*)d_in[26];
    const float* db3 = (const float*)d_in[27];
    float* out = (float*)d_out;

    float *xg1, *xg2, *xg3, *h1, *h2, *hst, *cst, *gbf, *prt, *a1, *a2;
    cudaGetSymbolAddress((void**)&xg1, g_xg1);
    cudaGetSymbolAddress((void**)&xg2, g_xg2);
    cudaGetSymbolAddress((void**)&xg3, g_xg3);
    cudaGetSymbolAddress((void**)&h1,  g_h1);
    cudaGetSymbolAddress((void**)&h2,  g_h2);
    cudaGetSymbolAddress((void**)&hst, g_hst);
    cudaGetSymbolAddress((void**)&cst, g_cst);
    cudaGetSymbolAddress((void**)&gbf, g_gbf);
    cudaGetSymbolAddress((void**)&prt, g_prt);
    cudaGetSymbolAddress((void**)&a1,  g_a1);
    cudaGetSymbolAddress((void**)&a2,  g_a2);

    const int Mall = BDIM * TDIM * LDIM;   // 131072
    const int Mst  = BDIM * LDIM;          // 4096
    dim3 blk(256);

    // ================= Layer 1: Cin=1, F=64 =================
    {
        dim3 grid(256 / BN + ((256 % BN) ? 1 : 0), Mall / BM);
        gemm_conv_kernel<<<dim3((256 + BN - 1) / BN, Mall / BM), blk>>>(
            x, Wx1, b1, xg1, Mall, 256, 3, 0, 1);
    }
    cudaMemsetAsync(hst, 0, (size_t)Mst * 64 * sizeof(float));
    cudaMemsetAsync(cst, 0, (size_t)Mst * 64 * sizeof(float));
    for (int t = 0; t < TDIM; t++) {
        gemm_conv_kernel<<<dim3((256 + BN - 1) / BN, Mst / BM), blk>>>(
            hst, Wh1, nullptr, gbf, Mst, 256, 192, 6, 1);
        int MF = Mst * 64;
        gate_kernel<<<(MF + 255) / 256, 256>>>(
            gbf, xg1, cst, hst, h1 + (size_t)t * MF, 64, 6, t, 1);
    }
    {
        size_t tot = (size_t)TDIM * Mst * 64;
        bn_kernel<<<(int)((tot + 255) / 256), 256>>>(h1, g1, be1, m1, v1, tot, 6);
    }

    // ================= Layer 2: Cin=64, F=128 =================
    gemm_conv_kernel<<<dim3((512 + BN - 1) / BN, Mall / BM), blk>>>(
        h1, Wx2, b2, xg2, Mall, 512, 192, 6, 1);
    cudaMemsetAsync(hst, 0, (size_t)Mst * 128 * sizeof(float));
    cudaMemsetAsync(cst, 0, (size_t)Mst * 128 * sizeof(float));
    for (int t = 0; t < TDIM; t++) {
        gemm_conv_kernel<<<dim3((512 + BN - 1) / BN, Mst / BM), blk>>>(
            hst, Wh2, nullptr, gbf, Mst, 512, 384, 7, 1);
        int MF = Mst * 128;
        gate_kernel<<<(MF + 255) / 256, 256>>>(
            gbf, xg2 + (size_t)t * Mst * 512, cst, hst, h2 + (size_t)t * MF, 128, 7, t, 0);
    }
    {
        size_t tot = (size_t)TDIM * Mst * 128;
        bn_kernel<<<(int)((tot + 255) / 256), 256>>>(h2, g2, be2, m2, v2, tot, 7);
    }

    // ================= Layer 3: Cin=128, F=256 (last step only) =================
    gemm_conv_kernel<<<dim3((1024 + BN - 1) / BN, Mall / BM), blk>>>(
        h2, Wx3, b3, xg3, Mall, 1024, 384, 7, 1);
    cudaMemsetAsync(hst, 0, (size_t)Mst * 256 * sizeof(float));
    cudaMemsetAsync(cst, 0, (size_t)Mst * 256 * sizeof(float));
    for (int t = 0; t < TDIM; t++) {
        gemm_conv_kernel<<<dim3((1024 + BN - 1) / BN, Mst / BM), blk>>>(
            hst, Wh3, nullptr, gbf, Mst, 1024, 768, 8, 1);
        int MF = Mst * 256;
        gate_kernel<<<(MF + 255) / 256, 256>>>(
            gbf, xg3 + (size_t)t * Mst * 1024, cst, hst, nullptr, 256, 8, t, 0);
    }
    {
        size_t tot = (size_t)Mst * 256;
        bn_kernel<<<(int)((tot + 255) / 256), 256>>>(hst, g3, be3, m3, v3, tot, 8);
    }

    // ================= Dense head =================
    fc_kernel<<<dim3(1024 / 64, 8), blk>>>(hst, D1, prt, 1024, 32768, 4096);
    fc_reduce_relu<<<(32 * 1024 + 255) / 256, 256>>>(prt, db1, a1, 1024, 8);
    fc_kernel<<<dim3(512 / 64, 2), blk>>>(a1, D2, prt, 512, 1024, 512);
    fc_reduce_relu<<<(32 * 512 + 255) / 256, 256>>>(prt, db2, a2, 512, 2);
    fc3_softmax<<<1, 256>>>(a2, D3, db3, out);
}

// round 6
// speedup vs baseline: 3.3483x; 3.3483x over previous
#include <cuda_runtime.h>
#include <cuda_bf16.h>
#include <math.h>
#include <cstdint>

#define BDIM 32
#define TDIM 32
#define LDIM 128
#define LOG_L 7

// ================= scratch (static device globals) =================
__device__ float g_xg1[(size_t)BDIM*TDIM*LDIM*256];   // [B][T][L][4F1]
__device__ float g_xg2[(size_t)TDIM*BDIM*LDIM*512];   // [T][B][L][4F2]
__device__ float g_xg3[(size_t)TDIM*BDIM*LDIM*1024];  // [T][B][L][4F3]
__device__ float g_h1 [(size_t)TDIM*BDIM*LDIM*64];    // [T][B][L][F1]
__device__ float g_h2 [(size_t)TDIM*BDIM*LDIM*128];   // [T][B][L][F2]
__device__ float g_hst[(size_t)BDIM*LDIM*256];
__device__ float g_cst[(size_t)BDIM*LDIM*256];
__device__ float g_gbf[(size_t)BDIM*LDIM*1024];
__device__ float g_prt[(size_t)8*BDIM*1024];
__device__ float g_a1 [(size_t)BDIM*1024];
__device__ float g_a2 [(size_t)BDIM*512];

// bf16 hi/lo activations
__device__ __nv_bfloat16 g_hhi[(size_t)BDIM*LDIM*256];
__device__ __nv_bfloat16 g_hlo[(size_t)BDIM*LDIM*256];
__device__ __nv_bfloat16 g_bn1h[(size_t)TDIM*BDIM*LDIM*64];
__device__ __nv_bfloat16 g_bn1l[(size_t)TDIM*BDIM*LDIM*64];
__device__ __nv_bfloat16 g_bn2h[(size_t)TDIM*BDIM*LDIM*128];
__device__ __nv_bfloat16 g_bn2l[(size_t)TDIM*BDIM*LDIM*128];

// bf16 hi/lo weights, [N,K] layout (row n = output channel, contiguous over K)
__device__ __nv_bfloat16 g_wh1h[256*192],  g_wh1l[256*192];
__device__ __nv_bfloat16 g_wx2h[512*192],  g_wx2l[512*192];
__device__ __nv_bfloat16 g_wh2h[512*384],  g_wh2l[512*384];
__device__ __nv_bfloat16 g_wx3h[1024*384], g_wx3l[1024*384];
__device__ __nv_bfloat16 g_wh3h[1024*768], g_wh3l[1024*768];

// ================= helpers =================
__device__ __forceinline__ uint32_t smem_to_u32(const void* p) {
    uint32_t a;
    asm("{ .reg .u64 t; cvta.to.shared.u64 t, %1; cvt.u32.u64 %0, t; }" : "=r"(a) : "l"(p));
    return a;
}
__device__ __forceinline__ void cp_async16(uint32_t saddr, const void* gaddr, uint32_t sz) {
    asm volatile("cp.async.cg.shared.global [%0], [%1], 16, %2;"
                 :: "r"(saddr), "l"(gaddr), "r"(sz));
}
#define CP_COMMIT() asm volatile("cp.async.commit_group;" ::: "memory")
#define CP_WAIT(n)  asm volatile("cp.async.wait_group %0;" :: "n"(n) : "memory")
#define LDSM_X4(r, addr) \
    asm volatile("ldmatrix.sync.aligned.m8n8.x4.shared.b16 {%0,%1,%2,%3}, [%4];" \
        : "=r"((r)[0]), "=r"((r)[1]), "=r"((r)[2]), "=r"((r)[3]) : "r"(addr))

__device__ __forceinline__ void mma16816(float* c, const uint32_t* a,
                                         uint32_t b0, uint32_t b1) {
    asm volatile("mma.sync.aligned.m16n8k16.row.col.f32.bf16.bf16.f32 "
        "{%0,%1,%2,%3}, {%4,%5,%6,%7}, {%8,%9}, {%0,%1,%2,%3};"
        : "+f"(c[0]), "+f"(c[1]), "+f"(c[2]), "+f"(c[3])
        : "r"(a[0]), "r"(a[1]), "r"(a[2]), "r"(a[3]), "r"(b0), "r"(b1));
}

// ================= HMMA compensated-bf16 implicit-conv GEMM =================
// C[M,N] = gather3(Ahi+Alo)[M,K] @ (Bhi+Blo)[N,K]^T (+bias)
// CTA tile 128x128, K-chunk 32, 8 warps (4M x 2N), warp tile 32x64.
// SMEM row stride 80B (32 bf16 + pad) -> conflict-free ldmatrix.
#define KC    32
#define SROW  80
#define TILE  (128*SROW)   // 10240
#define BUFSZ (4*TILE)     // Ahi, Alo, Bhi, Blo

__global__ __launch_bounds__(256) void mma_gemm_conv(
    const __nv_bfloat16* __restrict__ Ahi, const __nv_bfloat16* __restrict__ Alo,
    const __nv_bfloat16* __restrict__ Bhi, const __nv_bfloat16* __restrict__ Blo,
    const float* __restrict__ bias, float* __restrict__ C,
    int M, int N, int K, int logCin)
{
    extern __shared__ char smem[];
    const uint32_t sb = smem_to_u32(smem);
    const int tid  = threadIdx.x;
    const int wid  = tid >> 5;
    const int lane = tid & 31;
    const int wm   = wid >> 1;       // 0..3 -> M offset wm*32
    const int wn   = wid & 1;        // 0..1 -> N offset wn*64
    const int m0   = blockIdx.y * 128;
    const int n0   = blockIdx.x * 128;
    const int Cin  = 1 << logCin;
    const int nk   = K >> 5;

    float acc[2][8][4];
    #pragma unroll
    for (int mt = 0; mt < 2; mt++)
        #pragma unroll
        for (int nt = 0; nt < 8; nt++)
            #pragma unroll
            for (int r = 0; r < 4; r++) acc[mt][nt][r] = 0.f;

    auto load_chunk = [&](int c, int buf) {
        const int k0  = c << 5;
        const int ks  = k0 >> logCin;
        const int ci0 = k0 & (Cin - 1);
        const uint32_t sbuf = sb + buf * BUFSZ;
        #pragma unroll
        for (int i = 0; i < 2; i++) {
            int idx = tid + (i << 8);       // 0..511
            int row = idx >> 2;
            int seg = idx & 3;
            // ---- A (halo gather along L) ----
            int m  = m0 + row;
            int l  = m & (LDIM - 1);
            int ll = l + ks - 1;
            uint32_t sz = (ll >= 0 && ll < LDIM) ? 16u : 0u;
            int llc = ll < 0 ? 0 : (ll > LDIM - 1 ? LDIM - 1 : ll);
            size_t aoff = (size_t)(m - l + llc) * Cin + ci0 + seg * 8;
            uint32_t sa = sbuf + row * SROW + seg * 16;
            cp_async16(sa,            Ahi + aoff, sz);
            cp_async16(sa + TILE,     Alo + aoff, sz);
            // ---- B ----
            size_t boff = (size_t)(n0 + row) * K + k0 + seg * 8;
            cp_async16(sa + 2 * TILE, Bhi + boff, 16u);
            cp_async16(sa + 3 * TILE, Blo + boff, 16u);
        }
    };

    // per-thread ldmatrix address pieces
    const int a_row = lane & 15;
    const int a_k16 = (lane & 16) ? 16 : 0;
    const int b_row = (lane & 7) + ((lane & 16) ? 8 : 0);
    const int b_k16 = (lane & 8) ? 16 : 0;

    load_chunk(0, 0);
    CP_COMMIT();

    for (int c = 0; c < nk; c++) {
        if (c + 1 < nk) {
            load_chunk(c + 1, (c + 1) & 1);
            CP_COMMIT();
            CP_WAIT(1);
        } else {
            CP_WAIT(0);
        }
        __syncthreads();

        const uint32_t sbuf = sb + (c & 1) * BUFSZ;
        #pragma unroll
        for (int ks = 0; ks < 2; ks++) {
            uint32_t ah[2][4], al[2][4];
            #pragma unroll
            for (int mt = 0; mt < 2; mt++) {
                uint32_t ad = sbuf + (wm * 32 + mt * 16 + a_row) * SROW
                                   + ks * 32 + a_k16;
                LDSM_X4(ah[mt], ad);
                LDSM_X4(al[mt], ad + TILE);
            }
            #pragma unroll
            for (int n2 = 0; n2 < 4; n2++) {
                uint32_t bd = sbuf + 2 * TILE
                            + (wn * 64 + n2 * 16 + b_row) * SROW
                            + ks * 32 + b_k16;
                uint32_t bh[4], bl[4];
                LDSM_X4(bh, bd);
                LDSM_X4(bl, bd + TILE);
                #pragma unroll
                for (int mt = 0; mt < 2; mt++) {
                    mma16816(acc[mt][n2 * 2],     ah[mt], bh[0], bh[1]);
                    mma16816(acc[mt][n2 * 2],     ah[mt], bl[0], bl[1]);
                    mma16816(acc[mt][n2 * 2],     al[mt], bh[0], bh[1]);
                    mma16816(acc[mt][n2 * 2 + 1], ah[mt], bh[2], bh[3]);
                    mma16816(acc[mt][n2 * 2 + 1], ah[mt], bl[2], bl[3]);
                    mma16816(acc[mt][n2 * 2 + 1], al[mt], bh[2], bh[3]);
                }
            }
        }
        __syncthreads();
    }

    // ---- epilogue ----
    const int r0 = lane >> 2;
    const int cp = (lane & 3) * 2;
    #pragma unroll
    for (int mt = 0; mt < 2; mt++) {
        #pragma unroll
        for (int nt = 0; nt < 8; nt++) {
            int row = m0 + wm * 32 + mt * 16 + r0;
            int col = n0 + wn * 64 + nt * 8 + cp;
            float bx = 0.f, by = 0.f;
            if (bias) { bx = bias[col]; by = bias[col + 1]; }
            float2 v0 = make_float2(acc[mt][nt][0] + bx, acc[mt][nt][1] + by);
            float2 v1 = make_float2(acc[mt][nt][2] + bx, acc[mt][nt][3] + by);
            *reinterpret_cast<float2*>(C + (size_t)row * N + col)       = v0;
            *reinterpret_cast<float2*>(C + (size_t)(row + 8) * N + col) = v1;
        }
    }
}

// ================= weight convert: W[K,N] fp32 -> [N,K] bf16 hi/lo =================
__global__ void wconv_kernel(const float* __restrict__ W,
                             __nv_bfloat16* __restrict__ Bh, __nv_bfloat16* __restrict__ Bl,
                             int K, int N)
{
    int idx = blockIdx.x * blockDim.x + threadIdx.x;
    if (idx >= N * K) return;
    int n = idx / K, k = idx - n * K;
    float x = W[(size_t)k * N + n];
    __nv_bfloat16 hi = __float2bfloat16(x);
    Bh[idx] = hi;
    Bl[idx] = __float2bfloat16(x - __bfloat162float(hi));
}

// ================= fp32 implicit GEMM (layer-1 input, K=3) =================
#define BM 128
#define BN 128
#define BK 8
__global__ __launch_bounds__(256) void gemm_conv_kernel(
    const float* __restrict__ A, const float* __restrict__ W,
    const float* __restrict__ bias, float* __restrict__ C,
    int M, int N, int K, int logCin)
{
    __shared__ float As[BK][BM];
    __shared__ float Bs[BK][BN];
    int tid = threadIdx.x;
    int m0 = blockIdx.y * BM;
    int n0 = blockIdx.x * BN;
    int tx = tid & 15, ty = tid >> 4;
    int a_row = tid >> 1;
    int a_col = (tid & 1) * 4;
    int b_k = tid >> 5;
    int b_n = (tid & 31) * 4;
    int Cin = 1 << logCin;
    float acc[8][8];
    #pragma unroll
    for (int i = 0; i < 8; i++)
        #pragma unroll
        for (int j = 0; j < 8; j++) acc[i][j] = 0.f;
    for (int k0 = 0; k0 < K; k0 += BK) {
        int m = m0 + a_row;
        #pragma unroll
        for (int i = 0; i < 4; i++) {
            int kk = k0 + a_col + i;
            float v = 0.f;
            if (m < M && kk < K) {
                int l = m & (LDIM - 1);
                int ks = kk >> logCin;
                int ci = kk - (ks << logCin);
                int ll = l + ks - 1;
                if (ll >= 0 && ll < LDIM)
                    v = A[(size_t)(m - l + ll) * Cin + ci];
            }
            As[a_col + i][a_row] = v;
        }
        {
            int kk = k0 + b_k;
            float4 v = make_float4(0.f, 0.f, 0.f, 0.f);
            if (kk < K && n0 + b_n + 3 < N)
                v = *reinterpret_cast<const float4*>(&W[(size_t)kk * N + n0 + b_n]);
            Bs[b_k][b_n] = v.x; Bs[b_k][b_n+1] = v.y; Bs[b_k][b_n+2] = v.z; Bs[b_k][b_n+3] = v.w;
        }
        __syncthreads();
        #pragma unroll
        for (int kk = 0; kk < BK; kk++) {
            float af[8], bf[8];
            #pragma unroll
            for (int i = 0; i < 8; i++) af[i] = As[kk][ty * 8 + i];
            #pragma unroll
            for (int j = 0; j < 8; j++) bf[j] = Bs[kk][tx * 8 + j];
            #pragma unroll
            for (int i = 0; i < 8; i++)
                #pragma unroll
                for (int j = 0; j < 8; j++) acc[i][j] += af[i] * bf[j];
        }
        __syncthreads();
    }
    #pragma unroll
    for (int i = 0; i < 8; i++) {
        int m = m0 + ty * 8 + i;
        if (m >= M) continue;
        #pragma unroll
        for (int j = 0; j < 8; j++) {
            int n = n0 + tx * 8 + j;
            if (n >= N) continue;
            float v = acc[i][j];
            if (bias) v += bias[n];
            C[(size_t)m * N + n] = v;
        }
    }
}

// ================= LSTM gate fusion (emits fp32 h + bf16 hi/lo h) =================
__device__ __forceinline__ float hsig(float x) {
    return fminf(fmaxf(0.2f * x + 0.5f, 0.f), 1.f);
}
__global__ void gate_kernel(const float* __restrict__ g, const float* __restrict__ xg,
                            float* __restrict__ c, float* __restrict__ h,
                            float* __restrict__ hseq,
                            __nv_bfloat16* __restrict__ hhi, __nv_bfloat16* __restrict__ hlo,
                            int F, int logF, int t, int btLayout)
{
    int idx = blockIdx.x * blockDim.x + threadIdx.x;
    int MF = (BDIM * LDIM) << logF;
    if (idx >= MF) return;
    int m = idx >> logF;
    int f = idx - (m << logF);
    size_t xrow;
    if (btLayout) {
        int b = m >> LOG_L;
        int l = m & (LDIM - 1);
        xrow = ((size_t)(b * TDIM + t) << LOG_L) + l;
    } else {
        xrow = (size_t)m;
    }
    size_t gi = (size_t)m * 4 * F + f;
    size_t xi = xrow * 4 * F + f;
    float iv = g[gi]         + xg[xi];
    float fv = g[gi + F]     + xg[xi + F];
    float cv = g[gi + 2 * F] + xg[xi + 2 * F];
    float ov = g[gi + 3 * F] + xg[xi + 3 * F];
    float cn = hsig(fv) * c[idx] + hsig(iv) * fmaxf(cv, 0.f);
    c[idx] = cn;
    float hn = hsig(ov) * fmaxf(cn, 0.f);
    h[idx] = hn;
    __nv_bfloat16 hi = __float2bfloat16(hn);
    hhi[idx] = hi;
    hlo[idx] = __float2bfloat16(hn - __bfloat162float(hi));
    if (hseq) hseq[idx] = hn;
}

// ================= BN (fp32 in place) =================
__global__ void bn_kernel(float* __restrict__ x, const float* __restrict__ gw,
                          const float* __restrict__ be, const float* __restrict__ mu,
                          const float* __restrict__ var, size_t total, int logC)
{
    size_t idx = (size_t)blockIdx.x * blockDim.x + threadIdx.x;
    if (idx >= total) return;
    int C = 1 << logC;
    int ch = (int)(idx & (size_t)(C - 1));
    x[idx] = (x[idx] - mu[ch]) * rsqrtf(var[ch] + 1e-3f) * gw[ch] + be[ch];
}

// ================= BN -> bf16 hi/lo convert =================
__global__ void bn_convert(const float* __restrict__ x, const float* __restrict__ gw,
                           const float* __restrict__ be, const float* __restrict__ mu,
                           const float* __restrict__ var,
                           __nv_bfloat16* __restrict__ oh, __nv_bfloat16* __restrict__ ol,
                           size_t total, int logC)
{
    size_t idx = (size_t)blockIdx.x * blockDim.x + threadIdx.x;
    if (idx >= total) return;
    int C = 1 << logC;
    int ch = (int)(idx & (size_t)(C - 1));
    float v = (x[idx] - mu[ch]) * rsqrtf(var[ch] + 1e-3f) * gw[ch] + be[ch];
    __nv_bfloat16 hi = __float2bfloat16(v);
    oh[idx] = hi;
    ol[idx] = __float2bfloat16(v - __bfloat162float(hi));
}

// ================= dense head (fp32, small) =================
__global__ __launch_bounds__(256) void fc_kernel(
    const float* __restrict__ A, const float* __restrict__ W,
    float* __restrict__ partial, int N, int K, int kchunk)
{
    __shared__ float As[32][33];
    int tid = threadIdx.x;
    int n0 = blockIdx.x * 64;
    int col = tid & 63;
    int rq = tid >> 6;
    int k0 = blockIdx.y * kchunk;
    int kend = min(K, k0 + kchunk);
    float acc[8];
    #pragma unroll
    for (int r = 0; r < 8; r++) acc[r] = 0.f;
    int a_m = tid >> 3;
    int a_k = (tid & 7) * 4;
    for (int kb = k0; kb < kend; kb += 32) {
        #pragma unroll
        for (int i = 0; i < 4; i++) {
            int kk = kb + a_k + i;
            As[a_m][a_k + i] = (kk < K) ? A[(size_t)a_m * K + kk] : 0.f;
        }
        __syncthreads();
        #pragma unroll
        for (int kk = 0; kk < 32; kk++) {
            float w = W[(size_t)(kb + kk) * N + n0 + col];
            #pragma unroll
            for (int r = 0; r < 8; r++) acc[r] += As[rq * 8 + r][kk] * w;
        }
        __syncthreads();
    }
    #pragma unroll
    for (int r = 0; r < 8; r++) {
        int m = rq * 8 + r;
        partial[((size_t)blockIdx.y * 32 + m) * N + n0 + col] = acc[r];
    }
}

__global__ void fc_reduce_relu(const float* __restrict__ partial,
                               const float* __restrict__ bias,
                               float* __restrict__ out, int N, int KS)
{
    int idx = blockIdx.x * blockDim.x + threadIdx.x;
    if (idx >= 32 * N) return;
    int m = idx / N, n = idx - m * N;
    float s = bias[n];
    for (int ks = 0; ks < KS; ks++)
        s += partial[((size_t)ks * 32 + m) * N + n];
    out[idx] = fmaxf(s, 0.f);
}

__global__ void fc3_softmax(const float* __restrict__ A, const float* __restrict__ W,
                            const float* __restrict__ bias, float* __restrict__ out)
{
    __shared__ float logits[32][5];
    int tid = threadIdx.x;
    int bm = tid >> 3, j = tid & 7;
    if (bm < 32 && j < 5) {
        float s = bias[j];
        for (int k = 0; k < 512; k++)
            s += A[bm * 512 + k] * W[k * 5 + j];
        logits[bm][j] = s;
    }
    __syncthreads();
    if (bm < 32 && j == 0) {
        float mx = logits[bm][0];
        for (int q = 1; q < 5; q++) mx = fmaxf(mx, logits[bm][q]);
        float e[5], sum = 0.f;
        for (int q = 0; q < 5; q++) { e[q] = expf(logits[bm][q] - mx); sum += e[q]; }
        for (int q = 0; q < 5; q++) out[bm * 5 + q] = e[q] / sum;
    }
}

// ================= host orchestration =================
extern "C" void kernel_launch(void* const* d_in, const int* in_sizes, int n_in,
                              void* d_out, int out_size)
{
    const float* x   = (const float*)d_in[0];
    const float* Wx1 = (const float*)d_in[1];
    const float* Wh1 = (const float*)d_in[2];
    const float* b1  = (const float*)d_in[3];
    const float* Wx2 = (const float*)d_in[4];
    const float* Wh2 = (const float*)d_in[5];
    const float* b2  = (const float*)d_in[6];
    const float* Wx3 = (const float*)d_in[7];
    const float* Wh3 = (const float*)d_in[8];
    const float* b3  = (const float*)d_in[9];
    const float* g1  = (const float*)d_in[10];
    const float* be1 = (const float*)d_in[11];
    const float* m1  = (const float*)d_in[12];
    const float* v1  = (const float*)d_in[13];
    const float* g2  = (const float*)d_in[14];
    const float* be2 = (const float*)d_in[15];
    const float* m2  = (const float*)d_in[16];
    const float* v2  = (const float*)d_in[17];
    const float* g3  = (const float*)d_in[18];
    const float* be3 = (const float*)d_in[19];
    const float* m3  = (const float*)d_in[20];
    const float* v3  = (const float*)d_in[21];
    const float* D1  = (const float*)d_in[22];
    const float* db1 = (const float*)d_in[23];
    const float* D2  = (const float*)d_in[24];
    const float* db2 = (const float*)d_in[25];
    const float* D3  = (const float*)d_in[26];
    const float* db3 = (const float*)d_in[27];
    float* out = (float*)d_out;

    float *xg1, *xg2, *xg3, *h1, *h2, *hst, *cst, *gbf, *prt, *a1, *a2;
    __nv_bfloat16 *hhi, *hlo, *bn1h, *bn1l, *bn2h, *bn2l;
    __nv_bfloat16 *wh1h, *wh1l, *wx2h, *wx2l, *wh2h, *wh2l, *wx3h, *wx3l, *wh3h, *wh3l;
    cudaGetSymbolAddress((void**)&xg1, g_xg1);
    cudaGetSymbolAddress((void**)&xg2, g_xg2);
    cudaGetSymbolAddress((void**)&xg3, g_xg3);
    cudaGetSymbolAddress((void**)&h1,  g_h1);
    cudaGetSymbolAddress((void**)&h2,  g_h2);
    cudaGetSymbolAddress((void**)&hst, g_hst);
    cudaGetSymbolAddress((void**)&cst, g_cst);
    cudaGetSymbolAddress((void**)&gbf, g_gbf);
    cudaGetSymbolAddress((void**)&prt, g_prt);
    cudaGetSymbolAddress((void**)&a1,  g_a1);
    cudaGetSymbolAddress((void**)&a2,  g_a2);
    cudaGetSymbolAddress((void**)&hhi, g_hhi);
    cudaGetSymbolAddress((void**)&hlo, g_hlo);
    cudaGetSymbolAddress((void**)&bn1h, g_bn1h);
    cudaGetSymbolAddress((void**)&bn1l, g_bn1l);
    cudaGetSymbolAddress((void**)&bn2h, g_bn2h);
    cudaGetSymbolAddress((void**)&bn2l, g_bn2l);
    cudaGetSymbolAddress((void**)&wh1h, g_wh1h); cudaGetSymbolAddress((void**)&wh1l, g_wh1l);
    cudaGetSymbolAddress((void**)&wx2h, g_wx2h); cudaGetSymbolAddress((void**)&wx2l, g_wx2l);
    cudaGetSymbolAddress((void**)&wh2h, g_wh2h); cudaGetSymbolAddress((void**)&wh2l, g_wh2l);
    cudaGetSymbolAddress((void**)&wx3h, g_wx3h); cudaGetSymbolAddress((void**)&wx3l, g_wx3l);
    cudaGetSymbolAddress((void**)&wh3h, g_wh3h); cudaGetSymbolAddress((void**)&wh3l, g_wh3l);

    const int Mall = BDIM * TDIM * LDIM;   // 131072
    const int Mst  = BDIM * LDIM;          // 4096
    const int SMEM_MMA = 2 * BUFSZ;        // 81920
    cudaFuncSetAttribute(mma_gemm_conv, cudaFuncAttributeMaxDynamicSharedMemorySize, SMEM_MMA);
    dim3 blk(256);

    // ---- weight conversions ----
    wconv_kernel<<<(256*192  + 255)/256, 256>>>(Wh1, wh1h, wh1l, 192, 256);
    wconv_kernel<<<(512*192  + 255)/256, 256>>>(Wx2, wx2h, wx2l, 192, 512);
    wconv_kernel<<<(512*384  + 255)/256, 256>>>(Wh2, wh2h, wh2l, 384, 512);
    wconv_kernel<<<(1024*384 + 255)/256, 256>>>(Wx3, wx3h, wx3l, 384, 1024);
    wconv_kernel<<<(1024*768 + 255)/256, 256>>>(Wh3, wh3h, wh3l, 768, 1024);

    // ================= Layer 1 =================
    gemm_conv_kernel<<<dim3(2, Mall / BM), blk>>>(x, Wx1, b1, xg1, Mall, 256, 3, 0);
    cudaMemsetAsync(hhi, 0, (size_t)Mst * 64 * sizeof(__nv_bfloat16));
    cudaMemsetAsync(hlo, 0, (size_t)Mst * 64 * sizeof(__nv_bfloat16));
    cudaMemsetAsync(cst, 0, (size_t)Mst * 64 * sizeof(float));
    for (int t = 0; t < TDIM; t++) {
        mma_gemm_conv<<<dim3(2, Mst / 128), blk, SMEM_MMA>>>(
            hhi, hlo, wh1h, wh1l, nullptr, gbf, Mst, 256, 192, 6);
        int MF = Mst * 64;
        gate_kernel<<<(MF + 255) / 256, 256>>>(
            gbf, xg1, cst, hst, h1 + (size_t)t * MF, hhi, hlo, 64, 6, t, 1);
    }
    {
        size_t tot = (size_t)TDIM * Mst * 64;
        bn_convert<<<(int)((tot + 255) / 256), 256>>>(h1, g1, be1, m1, v1, bn1h, bn1l, tot, 6);
    }

    // ================= Layer 2 =================
    mma_gemm_conv<<<dim3(4, Mall / 128), blk, SMEM_MMA>>>(
        bn1h, bn1l, wx2h, wx2l, b2, xg2, Mall, 512, 192, 6);
    cudaMemsetAsync(hhi, 0, (size_t)Mst * 128 * sizeof(__nv_bfloat16));
    cudaMemsetAsync(hlo, 0, (size_t)Mst * 128 * sizeof(__nv_bfloat16));
    cudaMemsetAsync(cst, 0, (size_t)Mst * 128 * sizeof(float));
    for (int t = 0; t < TDIM; t++) {
        mma_gemm_conv<<<dim3(4, Mst / 128), blk, SMEM_MMA>>>(
            hhi, hlo, wh2h, wh2l, nullptr, gbf, Mst, 512, 384, 7);
        int MF = Mst * 128;
        gate_kernel<<<(MF + 255) / 256, 256>>>(
            gbf, xg2 + (size_t)t * Mst * 512, cst, hst, h2 + (size_t)t * MF, hhi, hlo, 128, 7, t, 0);
    }
    {
        size_t tot = (size_t)TDIM * Mst * 128;
        bn_convert<<<(int)((tot + 255) / 256), 256>>>(h2, g2, be2, m2, v2, bn2h, bn2l, tot, 7);
    }

    // ================= Layer 3 =================
    mma_gemm_conv<<<dim3(8, Mall / 128), blk, SMEM_MMA>>>(
        bn2h, bn2l, wx3h, wx3l, b3, xg3, Mall, 1024, 384, 7);
    cudaMemsetAsync(hhi, 0, (size_t)Mst * 256 * sizeof(__nv_bfloat16));
    cudaMemsetAsync(hlo, 0, (size_t)Mst * 256 * sizeof(__nv_bfloat16));
    cudaMemsetAsync(cst, 0, (size_t)Mst * 256 * sizeof(float));
    for (int t = 0; t < TDIM; t++) {
        mma_gemm_conv<<<dim3(8, Mst / 128), blk, SMEM_MMA>>>(
            hhi, hlo, wh3h, wh3l, nullptr, gbf, Mst, 1024, 768, 8);
        int MF = Mst * 256;
        gate_kernel<<<(MF + 255) / 256, 256>>>(
            gbf, xg3 + (size_t)t * Mst * 1024, cst, hst, nullptr, hhi, hlo, 256, 8, t, 0);
    }
    {
        size_t tot = (size_t)Mst * 256;
        bn_kernel<<<(int)((tot + 255) / 256), 256>>>(hst, g3, be3, m3, v3, tot, 8);
    }

    // ================= Dense head =================
    fc_kernel<<<dim3(1024 / 64, 8), blk>>>(hst, D1, prt, 1024, 32768, 4096);
    fc_reduce_relu<<<(32 * 1024 + 255) / 256, 256>>>(prt, db1, a1, 1024, 8);
    fc_kernel<<<dim3(512 / 64, 2), blk>>>(a1, D2, prt, 512, 1024, 512);
    fc_reduce_relu<<<(32 * 512 + 255) / 256, 256>>>(prt, db2, a2, 512, 2);
    fc3_softmax<<<1, 256>>>(a2, D3, db3, out);
}